// round 1
// baseline (speedup 1.0000x reference)
#include <cuda_runtime.h>

// BlockDiagAttention: B=4,H=16,N=4128,D=64. 64x64 diagonal attention blocks
// (+ one 32-row remainder block per head). fp32 in/out.
#define NSEQ   4128
#define TILES  65          // ceil(4128/64)
#define STRIDE 66          // 64 + 2 pad floats: conflict-free LDS.64 at lane row-stride 1

__device__ __forceinline__ unsigned long long ffma2(unsigned long long a,
                                                    unsigned long long b,
                                                    unsigned long long c) {
    unsigned long long d;
    asm("fma.rn.f32x2 %0, %1, %2, %3;" : "=l"(d) : "l"(a), "l"(b), "l"(c));
    return d;
}

__device__ __forceinline__ float2 unpack2(unsigned long long a) {
    float2 f;
    asm("mov.b64 {%0, %1}, %2;" : "=f"(f.x), "=f"(f.y) : "l"(a));
    return f;
}

extern __shared__ float smem_dyn[];

__global__ __launch_bounds__(256)
void bd_attn_kernel(const float* __restrict__ q, const float* __restrict__ k,
                    const float* __restrict__ v, float* __restrict__ out)
{
    float* smQ  = smem_dyn;                  // Q tile; later reused as P (probs)
    float* smK  = smem_dyn + 64 * STRIDE;    // K tile
    float* smVt = smem_dyn + 2 * 64 * STRIDE;// V tile, TRANSPOSED: Vt[j][m]

    const int tid  = threadIdx.x;
    const int bh   = blockIdx.x / TILES;
    const int t    = blockIdx.x % TILES;
    const int row0 = t * 64;
    const int nrows = min(64, NSEQ - row0);  // 64 or 32 (remainder)

    const size_t base = ((size_t)bh * NSEQ + row0) * 64;
    const float* qb = q + base;
    const float* kb = k + base;
    const float* vb = v + base;

    // ---- Load Q,K (row-major, padded) and V transposed. Zero-fill beyond nrows.
    for (int i = tid; i < 64 * 16; i += 256) {
        int r = i >> 4;
        int c = (i & 15) << 2;
        float4 zq = make_float4(0.f, 0.f, 0.f, 0.f);
        float4 zk = zq, zv = zq;
        if (r < nrows) {
            zq = *(const float4*)(qb + r * 64 + c);
            zk = *(const float4*)(kb + r * 64 + c);
            zv = *(const float4*)(vb + r * 64 + c);
        }
        float* dq = &smQ[r * STRIDE + c];
        *(float2*)(dq)     = make_float2(zq.x, zq.y);
        *(float2*)(dq + 2) = make_float2(zq.z, zq.w);
        float* dk = &smK[r * STRIDE + c];
        *(float2*)(dk)     = make_float2(zk.x, zk.y);
        *(float2*)(dk + 2) = make_float2(zk.z, zk.w);
        smVt[(c + 0) * STRIDE + r] = zv.x;
        smVt[(c + 1) * STRIDE + r] = zv.y;
        smVt[(c + 2) * STRIDE + r] = zv.z;
        smVt[(c + 3) * STRIDE + r] = zv.w;
    }
    __syncthreads();

    const int tx = tid & 15;   // col group
    const int ty = tid >> 4;   // row group
    // thread owns rows i = ty + 16*r, cols j = tx + 16*c (r,c in 0..3)

    // ---- S = Q K^T  (packed f32x2 along d)
    unsigned long long acc[4][4];
#pragma unroll
    for (int r = 0; r < 4; ++r)
#pragma unroll
        for (int c = 0; c < 4; ++c) acc[r][c] = 0ull;

#pragma unroll 4
    for (int dd = 0; dd < 32; ++dd) {
        unsigned long long q2[4], k2[4];
#pragma unroll
        for (int r = 0; r < 4; ++r)
            q2[r] = *(const unsigned long long*)&smQ[(ty + 16 * r) * STRIDE + 2 * dd];
#pragma unroll
        for (int c = 0; c < 4; ++c)
            k2[c] = *(const unsigned long long*)&smK[(tx + 16 * c) * STRIDE + 2 * dd];
#pragma unroll
        for (int r = 0; r < 4; ++r)
#pragma unroll
            for (int c = 0; c < 4; ++c)
                acc[r][c] = ffma2(q2[r], k2[c], acc[r][c]);
    }
    __syncthreads();   // all Q reads done; smQ becomes the P buffer

    // ---- store raw scores into P
#pragma unroll
    for (int r = 0; r < 4; ++r)
#pragma unroll
        for (int c = 0; c < 4; ++c) {
            float2 f = unpack2(acc[r][c]);
            smQ[(ty + 16 * r) * STRIDE + (tx + 16 * c)] = f.x + f.y;
        }
    __syncthreads();

    // ---- row softmax (scale 1/8, mask cols >= nrows). One warp per 8 rows.
    {
        const int w = tid >> 5, l = tid & 31;
        for (int rr = 0; rr < 8; ++rr) {
            float* row = &smQ[(w * 8 + rr) * STRIDE];
            const bool va = l < nrows;
            const bool vb2 = (l + 32) < nrows;
            float a = va  ? row[l]      * 0.125f : -1e30f;
            float b = vb2 ? row[l + 32] * 0.125f : -1e30f;
            float m = fmaxf(a, b);
#pragma unroll
            for (int o = 16; o; o >>= 1) m = fmaxf(m, __shfl_xor_sync(0xffffffffu, m, o));
            float ea = va  ? __expf(a - m) : 0.f;
            float eb = vb2 ? __expf(b - m) : 0.f;
            float s = ea + eb;
#pragma unroll
            for (int o = 16; o; o >>= 1) s += __shfl_xor_sync(0xffffffffu, s, o);
            float inv = __frcp_rn(s);
            row[l]      = ea * inv;
            row[l + 32] = eb * inv;
        }
    }
    __syncthreads();

    // ---- O = P V  (packed f32x2 along m, V transposed in smem)
#pragma unroll
    for (int r = 0; r < 4; ++r)
#pragma unroll
        for (int c = 0; c < 4; ++c) acc[r][c] = 0ull;

#pragma unroll 4
    for (int mm = 0; mm < 32; ++mm) {
        unsigned long long p2[4], v2[4];
#pragma unroll
        for (int r = 0; r < 4; ++r)
            p2[r] = *(const unsigned long long*)&smQ[(ty + 16 * r) * STRIDE + 2 * mm];
#pragma unroll
        for (int c = 0; c < 4; ++c)
            v2[c] = *(const unsigned long long*)&smVt[(tx + 16 * c) * STRIDE + 2 * mm];
#pragma unroll
        for (int r = 0; r < 4; ++r)
#pragma unroll
            for (int c = 0; c < 4; ++c)
                acc[r][c] = ffma2(p2[r], v2[c], acc[r][c]);
    }

    float* ob = out + base;
#pragma unroll
    for (int r = 0; r < 4; ++r) {
        int i = ty + 16 * r;
        if (i < nrows) {
#pragma unroll
            for (int c = 0; c < 4; ++c) {
                float2 f = unpack2(acc[r][c]);
                ob[i * 64 + (tx + 16 * c)] = f.x + f.y;
            }
        }
    }
}

extern "C" void kernel_launch(void* const* d_in, const int* in_sizes, int n_in,
                              void* d_out, int out_size) {
    const float* q = (const float*)d_in[0];
    const float* k = (const float*)d_in[1];
    const float* v = (const float*)d_in[2];
    float* out = (float*)d_out;

    const int bh = in_sizes[0] / (NSEQ * 64);      // B*H = 64
    const int smem_bytes = 3 * 64 * STRIDE * (int)sizeof(float);  // 50688

    cudaFuncSetAttribute(bd_attn_kernel,
                         cudaFuncAttributeMaxDynamicSharedMemorySize, smem_bytes);
    bd_attn_kernel<<<bh * TILES, 256, smem_bytes>>>(q, k, v, out);
}